// round 4
// baseline (speedup 1.0000x reference)
#include <cuda_runtime.h>
#include <cuda_bf16.h>
#include <cstdint>
#include <math.h>

#define BS   32768
#define NQ   8
#define FFN  2048
#define EMB  512

#define TMT  128              // tokens per CTA
#define TNT  128              // out cols per CTA
#define KC   32               // FFN chunk per iteration (2 x k16 mma steps)
#define NC   (FFN / KC)       // 64 iterations
#define NTH  256
#define ROWB 80               // 64B data + 16B pad -> ldmatrix conflict-free

// W2 transposed + bf16 hi/lo split: [EMB][FFN]
__device__ __nv_bfloat16 g_w2t_hi[EMB * FFN];
__device__ __nv_bfloat16 g_w2t_lo[EMB * FFN];

// ---- smem layout (byte offsets into dynamic smem) ----
#define SM_AHI(b) ((b) * 10240)              // 2 bufs  (128 rows * 80B)
#define SM_ALO(b) (20480 + (b) * 10240)      // 2 bufs
#define SM_BHI(b) (40960 + (b) * 10240)      // 3 bufs
#define SM_BLO(b) (71680 + (b) * 10240)      // 3 bufs
#define SM_W1(b)  (102400 + (b) * 1024)      // 4 bufs, [32][8] fp32
#define SM_B1(b)  (106496 + (b) * 128)       // 4 bufs, 32 fp32
#define SMEM_BYTES 107008

__device__ __forceinline__ uint32_t smem_u32(const void* p) {
    uint32_t a;
    asm("{ .reg .u64 t; cvta.to.shared.u64 t, %1; cvt.u32.u64 %0, t; }" : "=r"(a) : "l"(p));
    return a;
}

#define LDSM4(r, a)                                                            \
    asm volatile("ldmatrix.sync.aligned.m8n8.x4.shared.b16 {%0,%1,%2,%3}, [%4];" \
        : "=r"((r)[0]), "=r"((r)[1]), "=r"((r)[2]), "=r"((r)[3]) : "r"(a))

#define MMA16816(d, a, b0, b1v)                                                \
    asm volatile("mma.sync.aligned.m16n8k16.row.col.f32.bf16.bf16.f32 "       \
        "{%0,%1,%2,%3},{%4,%5,%6,%7},{%8,%9},{%0,%1,%2,%3};"                  \
        : "+f"((d)[0]), "+f"((d)[1]), "+f"((d)[2]), "+f"((d)[3])              \
        : "r"((a)[0]), "r"((a)[1]), "r"((a)[2]), "r"((a)[3]), "r"(b0), "r"(b1v))

#define CP16(dst, src)                                                         \
    asm volatile("cp.async.cg.shared.global [%0], [%1], 16;" :: "r"(dst), "l"(src))
#define CP4(dst, src)                                                          \
    asm volatile("cp.async.ca.shared.global [%0], [%1], 4;" :: "r"(dst), "l"(src))
#define CP_COMMIT() asm volatile("cp.async.commit_group;" ::: "memory")
#define CP_WAIT0()  asm volatile("cp.async.wait_group 0;" ::: "memory")
#define CP_WAIT1()  asm volatile("cp.async.wait_group 1;" ::: "memory")

// ---- prep: W2 [FFN][EMB] fp32 -> bf16 hi/lo transposed [EMB][FFN] ----------
__global__ void prep_w2_kernel(const float* __restrict__ W2) {
    int t = blockIdx.x * blockDim.x + threadIdx.x;
    if (t >= EMB * FFN) return;
    int n = t >> 11;
    int k = t & (FFN - 1);
    float v = W2[(size_t)k * EMB + n];
    __nv_bfloat16 h = __float2bfloat16(v);
    g_w2t_hi[t] = h;
    g_w2t_lo[t] = __float2bfloat16(v - __bfloat162float(h));
}

// ---- main fused kernel ------------------------------------------------------
__global__ __launch_bounds__(NTH, 2)
void ffq_mma_kernel(const float* __restrict__ x,
                    const float* __restrict__ theta,
                    const float* __restrict__ W1,
                    const float* __restrict__ b1g,
                    const float* __restrict__ b2,
                    float* __restrict__ out)
{
    extern __shared__ char sm[];
    const uint32_t smb = smem_u32(sm);

    const int tid  = threadIdx.x;
    const int wid  = tid >> 5;
    const int lane = tid & 31;
    const int row0 = blockIdx.x * TMT;
    const int col0 = blockIdx.y * TNT;
    const int wm   = wid & 3;        // M group (32 rows)
    const int wn   = wid >> 2;       // N group (64 cols)

    // per-thread q row (held in regs for the whole K loop)
    const int qm = tid >> 1;         // token row 0..127
    const int kh = tid & 1;          // which 16-k half of the 32-chunk
    float q[NQ];
    {
        const float* xr = x + (size_t)(row0 + qm) * NQ;
        #pragma unroll
        for (int j = 0; j < NQ; j++)
            q[j] = cosf(xr[j]) * cosf(__ldg(&theta[j]));
    }

    // ldmatrix lane addresses (within a buffer)
    const uint32_t a_off = (uint32_t)(wm * 32 + (lane & 15)) * ROWB + ((lane >> 4) << 4);
    const uint32_t b_off = (uint32_t)(wn * 64 + (lane & 7) + ((lane & 16) >> 1)) * ROWB
                         + ((lane & 8) << 1);

    float acc[2][8][4];
    #pragma unroll
    for (int a = 0; a < 2; a++)
        #pragma unroll
        for (int b = 0; b < 8; b++)
            #pragma unroll
            for (int i = 0; i < 4; i++) acc[a][b][i] = 0.f;

    // ---- async staging helpers ----
    auto issue_w1 = [&](int chunk, int buf) {
        int k = tid >> 3, j = tid & 7;   // all 256 threads, one 4B word each
        CP4(smb + SM_W1(buf) + k * 32 + j * 4,
            (const char*)(W1 + (size_t)j * FFN + chunk * KC + k));
        if (tid < KC)
            CP4(smb + SM_B1(buf) + tid * 4, (const char*)(b1g + chunk * KC + tid));
    };
    auto issue_w2 = [&](int chunk, int buf) {
        int n = tid >> 1, hs = tid & 1;
        size_t ge = (size_t)(col0 + n) * FFN + chunk * KC + hs * 16;
        uint32_t wo = (uint32_t)n * ROWB + hs * 32;
        CP16(smb + SM_BHI(buf) + wo,      (const char*)(g_w2t_hi + ge));
        CP16(smb + SM_BHI(buf) + wo + 16, (const char*)(g_w2t_hi + ge + 8));
        CP16(smb + SM_BLO(buf) + wo,      (const char*)(g_w2t_lo + ge));
        CP16(smb + SM_BLO(buf) + wo + 16, (const char*)(g_w2t_lo + ge + 8));
    };
    // compute h chunk (32 k-values over 128 rows) -> split bf16 hi/lo -> A buf
    auto produce = [&](int pa, int wb) {
        const float* w1c = (const float*)(sm + SM_W1(wb));
        const float* b1c = (const float*)(sm + SM_B1(wb));
        uint32_t hh[8], hl[8];
        #pragma unroll
        for (int u = 0; u < 16; u++) {
            int k = kh * 16 + u;
            float4 wa = *(const float4*)&w1c[k * 8];       // broadcast LDS
            float4 wb4 = *(const float4*)&w1c[k * 8 + 4];
            float s = b1c[k];
            s = fmaf(q[0], wa.x, s);  s = fmaf(q[1], wa.y, s);
            s = fmaf(q[2], wa.z, s);  s = fmaf(q[3], wa.w, s);
            s = fmaf(q[4], wb4.x, s); s = fmaf(q[5], wb4.y, s);
            s = fmaf(q[6], wb4.z, s); s = fmaf(q[7], wb4.w, s);
            s = fmaxf(s, 0.f);
            __nv_bfloat16 bh = __float2bfloat16(s);
            float rem = s - __bfloat162float(bh);
            __nv_bfloat16 bl = __float2bfloat16(rem);
            uint32_t uh = (uint32_t)__bfloat16_as_ushort(bh);
            uint32_t ul = (uint32_t)__bfloat16_as_ushort(bl);
            if (u & 1) { hh[u >> 1] |= uh << 16; hl[u >> 1] |= ul << 16; }
            else       { hh[u >> 1]  = uh;       hl[u >> 1]  = ul;       }
        }
        uint32_t ho = (uint32_t)qm * ROWB + kh * 32;
        *(uint4*)(sm + SM_AHI(pa) + ho)      = make_uint4(hh[0], hh[1], hh[2], hh[3]);
        *(uint4*)(sm + SM_AHI(pa) + ho + 16) = make_uint4(hh[4], hh[5], hh[6], hh[7]);
        *(uint4*)(sm + SM_ALO(pa) + ho)      = make_uint4(hl[0], hl[1], hl[2], hl[3]);
        *(uint4*)(sm + SM_ALO(pa) + ho + 16) = make_uint4(hl[4], hl[5], hl[6], hl[7]);
    };

    // ---- prologue: stage W1 chunks 0-2, W2 chunks 0-1; produce A chunk 0 ----
    issue_w1(0, 0); issue_w1(1, 1); issue_w1(2, 2);
    issue_w2(0, 0); issue_w2(1, 1);
    CP_COMMIT(); CP_WAIT0();
    __syncthreads();
    produce(0, 0);
    __syncthreads();

    // ---- main loop: one commit group per iteration, wait_group 1 ----
    for (int c = 0; c < NC; c++) {
        const int pa = c & 1;
        const int pb = c % 3;

        // issue prefetches (W2 at distance 2, W1 at distance 3)
        if (c + 2 < NC) issue_w2(c + 2, (c + 2) % 3);
        if (c + 3 < NC) issue_w1(c + 3, (c + 3) & 3);
        CP_COMMIT();

        // consume chunk c: ldmatrix + 96 MMAs (acc-reuse distance 4)
        {
            const uint32_t Ah = smb + SM_AHI(pa) + a_off;
            const uint32_t Al = smb + SM_ALO(pa) + a_off;
            const uint32_t Bh = smb + SM_BHI(pb) + b_off;
            const uint32_t Bl = smb + SM_BLO(pb) + b_off;
            #pragma unroll
            for (int ks = 0; ks < 2; ks++) {
                uint32_t ah[2][4], al[2][4];
                LDSM4(ah[0], Ah + ks * 32);
                LDSM4(ah[1], Ah + ks * 32 + 16 * ROWB);
                LDSM4(al[0], Al + ks * 32);
                LDSM4(al[1], Al + ks * 32 + 16 * ROWB);
                #pragma unroll
                for (int g = 0; g < 4; g++) {
                    uint32_t bh[4], bl[4];
                    LDSM4(bh, Bh + g * 16 * ROWB + ks * 32);
                    LDSM4(bl, Bl + g * 16 * ROWB + ks * 32);
                    // hi*hi
                    MMA16816(acc[0][2 * g],     ah[0], bh[0], bh[1]);
                    MMA16816(acc[1][2 * g],     ah[1], bh[0], bh[1]);
                    MMA16816(acc[0][2 * g + 1], ah[0], bh[2], bh[3]);
                    MMA16816(acc[1][2 * g + 1], ah[1], bh[2], bh[3]);
                    // hi*lo
                    MMA16816(acc[0][2 * g],     ah[0], bl[0], bl[1]);
                    MMA16816(acc[1][2 * g],     ah[1], bl[0], bl[1]);
                    MMA16816(acc[0][2 * g + 1], ah[0], bl[2], bl[3]);
                    MMA16816(acc[1][2 * g + 1], ah[1], bl[2], bl[3]);
                    // lo*hi
                    MMA16816(acc[0][2 * g],     al[0], bh[0], bh[1]);
                    MMA16816(acc[1][2 * g],     al[1], bh[0], bh[1]);
                    MMA16816(acc[0][2 * g + 1], al[0], bh[2], bh[3]);
                    MMA16816(acc[1][2 * g + 1], al[1], bh[2], bh[3]);
                }
            }
        }

        // produce chunk c+1 into the other A buffer
        if (c + 1 < NC) produce((c + 1) & 1, (c + 1) & 3);

        CP_WAIT1();            // newest group (c+2/c+3) may stay in flight
        __syncthreads();
    }

    // ---- epilogue: D frags + b2 -> gmem ----
    #pragma unroll
    for (int mt = 0; mt < 2; mt++) {
        int mrow = row0 + wm * 32 + mt * 16 + (lane >> 2);
        #pragma unroll
        for (int nt = 0; nt < 8; nt++) {
            int ncol = col0 + wn * 64 + nt * 8 + (lane & 3) * 2;
            float bx = b2[ncol], by = b2[ncol + 1];
            float2 v0 = make_float2(acc[mt][nt][0] + bx, acc[mt][nt][1] + by);
            float2 v1 = make_float2(acc[mt][nt][2] + bx, acc[mt][nt][3] + by);
            *(float2*)&out[(size_t)mrow * EMB + ncol]       = v0;
            *(float2*)&out[(size_t)(mrow + 8) * EMB + ncol] = v1;
        }
    }
}

// ---- launcher ----------------------------------------------------------------
extern "C" void kernel_launch(void* const* d_in, const int* in_sizes, int n_in,
                              void* d_out, int out_size)
{
    const float *x = 0, *theta = 0, *W1 = 0, *b1 = 0, *W2 = 0, *b2 = 0;
    for (int i = 0; i < n_in; i++) {
        switch (in_sizes[i]) {
            case BS * NQ:   x     = (const float*)d_in[i]; break;
            case NQ:        theta = (const float*)d_in[i]; break;
            case NQ * FFN:  W1    = (const float*)d_in[i]; break;
            case FFN:       b1    = (const float*)d_in[i]; break;
            case FFN * EMB: W2    = (const float*)d_in[i]; break;
            case EMB:       b2    = (const float*)d_in[i]; break;
            default: break;
        }
    }

    prep_w2_kernel<<<(EMB * FFN + 255) / 256, 256>>>(W2);

    cudaFuncSetAttribute(ffq_mma_kernel, cudaFuncAttributeMaxDynamicSharedMemorySize,
                         SMEM_BYTES);
    dim3 grid(BS / TMT, EMB / TNT);   // 256 x 4 = 1024 CTAs
    ffq_mma_kernel<<<grid, NTH, SMEM_BYTES>>>(x, theta, W1, b1, b2, (float*)d_out);
}

// round 5
// speedup vs baseline: 1.3826x; 1.3826x over previous
#include <cuda_runtime.h>
#include <cuda_fp16.h>
#include <cstdint>
#include <math.h>

#define BS   32768
#define NQ   8
#define FFN  2048
#define EMB  512

#define TMT  128              // tokens per CTA (GEMM)
#define TNT  128              // out cols per CTA
#define KC   32               // FFN chunk per iteration (2 x k16 mma steps)
#define NC   (FFN / KC)       // 64 iterations
#define NTH  256
#define ROWB 80               // 64B data + 16B pad (r*20 mod 32 distinct -> ldmatrix conflict-free)
#define NSTAGE 3

// scratch: H (fp16 of relu(q@W1+b1)) and W2 transposed + fp16 hi/lo split
__device__ __half g_h[BS * FFN];
__device__ __half g_w2t_hi[EMB * FFN];
__device__ __half g_w2t_lo[EMB * FFN];

// ---- smem layout for GEMM (byte offsets into dynamic smem) ----
#define SM_A(s)  ((s) * 10240)               // 128 rows * 80B
#define SM_BH(s) (30720 + (s) * 10240)
#define SM_BL(s) (61440 + (s) * 10240)
#define SMEM_BYTES 92160

__device__ __forceinline__ uint32_t smem_u32(const void* p) {
    uint32_t a;
    asm("{ .reg .u64 t; cvta.to.shared.u64 t, %1; cvt.u32.u64 %0, t; }" : "=r"(a) : "l"(p));
    return a;
}

#define LDSM4(r, a)                                                            \
    asm volatile("ldmatrix.sync.aligned.m8n8.x4.shared.b16 {%0,%1,%2,%3}, [%4];" \
        : "=r"((r)[0]), "=r"((r)[1]), "=r"((r)[2]), "=r"((r)[3]) : "r"(a))

#define MMAF16(d, a, b0, b1v)                                                  \
    asm volatile("mma.sync.aligned.m16n8k16.row.col.f32.f16.f16.f32 "         \
        "{%0,%1,%2,%3},{%4,%5,%6,%7},{%8,%9},{%0,%1,%2,%3};"                  \
        : "+f"((d)[0]), "+f"((d)[1]), "+f"((d)[2]), "+f"((d)[3])              \
        : "r"((a)[0]), "r"((a)[1]), "r"((a)[2]), "r"((a)[3]), "r"(b0), "r"(b1v))

#define CP16(dst, src)                                                         \
    asm volatile("cp.async.cg.shared.global [%0], [%1], 16;" :: "r"(dst), "l"(src))
#define CP_COMMIT() asm volatile("cp.async.commit_group;" ::: "memory")
#define CP_WAIT0()  asm volatile("cp.async.wait_group 0;" ::: "memory")
#define CP_WAIT1()  asm volatile("cp.async.wait_group 1;" ::: "memory")

// ---- prep: W2 [FFN][EMB] fp32 -> fp16 hi/lo transposed [EMB][FFN] ----------
__global__ void prep_w2_kernel(const float* __restrict__ W2) {
    int t = blockIdx.x * blockDim.x + threadIdx.x;
    if (t >= EMB * FFN) return;
    int n = t >> 11;
    int k = t & (FFN - 1);
    float v = W2[(size_t)k * EMB + n];
    __half h = __float2half_rn(v);
    g_w2t_hi[t] = h;
    g_w2t_lo[t] = __float2half_rn(v - __half2float(h));
}

// ---- kernel 1: H = fp16(relu(q @ W1 + b1)), q = cos(x)*cos(theta) ----------
// Block: 256 threads, 64 tokens. Thread owns 8 consecutive FFN columns
// (W1 slice + b1 held in registers); q broadcast from smem.
#define TB 64
__global__ __launch_bounds__(256, 4)
void h_kernel(const float* __restrict__ x,
              const float* __restrict__ theta,
              const float* __restrict__ W1,
              const float* __restrict__ b1)
{
    __shared__ float q_s[TB][NQ];
    const int tid  = threadIdx.x;
    const int row0 = blockIdx.x * TB;
    const int k0   = tid * 8;               // this thread's 8 FFN columns

    // stage q for 64 tokens
    #pragma unroll
    for (int i = tid; i < TB * NQ; i += 256) {
        int m = i >> 3, j = i & 7;
        q_s[m][j] = cosf(x[(size_t)(row0 + m) * NQ + j]) * cosf(__ldg(&theta[j]));
    }

    // W1 slice [8 j][8 u] and b1 slice into registers
    float w1r[8][NQ];
    float b1r[8];
    #pragma unroll
    for (int u = 0; u < 8; u++) {
        b1r[u] = __ldg(&b1[k0 + u]);
        #pragma unroll
        for (int j = 0; j < NQ; j++)
            w1r[u][j] = __ldg(&W1[(size_t)j * FFN + k0 + u]);
    }
    __syncthreads();

    for (int t = 0; t < TB; t++) {
        float4 qa = *(const float4*)&q_s[t][0];   // broadcast LDS
        float4 qb = *(const float4*)&q_s[t][4];
        uint32_t w[4];
        #pragma unroll
        for (int u = 0; u < 8; u++) {
            float s = b1r[u];
            s = fmaf(qa.x, w1r[u][0], s); s = fmaf(qa.y, w1r[u][1], s);
            s = fmaf(qa.z, w1r[u][2], s); s = fmaf(qa.w, w1r[u][3], s);
            s = fmaf(qb.x, w1r[u][4], s); s = fmaf(qb.y, w1r[u][5], s);
            s = fmaf(qb.z, w1r[u][6], s); s = fmaf(qb.w, w1r[u][7], s);
            s = fmaxf(s, 0.f);
            uint32_t hb = (uint32_t)__half_as_ushort(__float2half_rn(s));
            if (u & 1) w[u >> 1] |= hb << 16;
            else       w[u >> 1]  = hb;
        }
        // coalesced: consecutive threads -> consecutive 16B within the token row
        *(uint4*)((char*)(g_h + (size_t)(row0 + t) * FFN) + tid * 16)
            = make_uint4(w[0], w[1], w[2], w[3]);
    }
}

// ---- kernel 2: out = H @ W2 + b2, 2-term fp16 (A single, B hi/lo) ----------
__global__ __launch_bounds__(NTH, 2)
void gemm_kernel(const float* __restrict__ b2, float* __restrict__ out)
{
    extern __shared__ char sm[];
    const uint32_t smb = smem_u32(sm);

    const int tid  = threadIdx.x;
    const int wid  = tid >> 5;
    const int lane = tid & 31;
    const int col0 = blockIdx.x * TNT;      // x fastest: 4 col CTAs share A via L2
    const int row0 = blockIdx.y * TMT;
    const int wm   = wid & 3;               // M group (32 rows)
    const int wn   = wid >> 2;              // N group (64 cols)

    // ldmatrix lane addresses (verified mapping from R3)
    const uint32_t a_off = (uint32_t)(wm * 32 + (lane & 15)) * ROWB + ((lane >> 4) << 4);
    const uint32_t b_off = (uint32_t)(wn * 64 + (lane & 7) + ((lane & 16) >> 1)) * ROWB
                         + ((lane & 8) << 1);

    // cp.async addressing: thread covers row = tid>>1, k-half = tid&1 (16 fp16 = 32B)
    const int ldr = tid >> 1;
    const int ldh = tid & 1;
    const __half* gA  = g_h      + (size_t)(row0 + ldr) * FFN + ldh * 16;
    const __half* gBh = g_w2t_hi + (size_t)(col0 + ldr) * FFN + ldh * 16;
    const __half* gBl = g_w2t_lo + (size_t)(col0 + ldr) * FFN + ldh * 16;
    const uint32_t so = (uint32_t)ldr * ROWB + ldh * 32;

    auto issue = [&](int chunk, int s) {
        const char* a  = (const char*)(gA  + chunk * KC);
        const char* bh = (const char*)(gBh + chunk * KC);
        const char* bl = (const char*)(gBl + chunk * KC);
        CP16(smb + SM_A(s)  + so,      a);
        CP16(smb + SM_A(s)  + so + 16, a + 16);
        CP16(smb + SM_BH(s) + so,      bh);
        CP16(smb + SM_BH(s) + so + 16, bh + 16);
        CP16(smb + SM_BL(s) + so,      bl);
        CP16(smb + SM_BL(s) + so + 16, bl + 16);
    };

    float acc[2][8][4];
    #pragma unroll
    for (int a = 0; a < 2; a++)
        #pragma unroll
        for (int b = 0; b < 8; b++)
            #pragma unroll
            for (int i = 0; i < 4; i++) acc[a][b][i] = 0.f;

    // prologue
    issue(0, 0); CP_COMMIT();
    issue(1, 1); CP_COMMIT();
    CP_WAIT1();                 // stage 0 landed
    __syncthreads();

    for (int c = 0; c < NC; c++) {
        const int s = c % NSTAGE;

        if (c + 2 < NC) issue(c + 2, (c + 2) % NSTAGE);
        CP_COMMIT();

        // consume stage s: 64 MMAs per warp
        const uint32_t A  = smb + SM_A(s)  + a_off;
        const uint32_t Bh = smb + SM_BH(s) + b_off;
        const uint32_t Bl = smb + SM_BL(s) + b_off;
        #pragma unroll
        for (int ks = 0; ks < 2; ks++) {
            uint32_t ah[2][4];
            LDSM4(ah[0], A + ks * 32);
            LDSM4(ah[1], A + ks * 32 + 16 * ROWB);
            #pragma unroll
            for (int g = 0; g < 4; g++) {
                uint32_t bh[4], bl[4];
                LDSM4(bh, Bh + g * 16 * ROWB + ks * 32);
                LDSM4(bl, Bl + g * 16 * ROWB + ks * 32);
                MMAF16(acc[0][2 * g],     ah[0], bh[0], bh[1]);
                MMAF16(acc[1][2 * g],     ah[1], bh[0], bh[1]);
                MMAF16(acc[0][2 * g + 1], ah[0], bh[2], bh[3]);
                MMAF16(acc[1][2 * g + 1], ah[1], bh[2], bh[3]);
                MMAF16(acc[0][2 * g],     ah[0], bl[0], bl[1]);
                MMAF16(acc[1][2 * g],     ah[1], bl[0], bl[1]);
                MMAF16(acc[0][2 * g + 1], ah[0], bl[2], bl[3]);
                MMAF16(acc[1][2 * g + 1], ah[1], bl[2], bl[3]);
            }
        }

        CP_WAIT1();             // stage c+1 landed; c+2 may stay in flight
        __syncthreads();
    }

    // epilogue: D frags + b2
    #pragma unroll
    for (int mt = 0; mt < 2; mt++) {
        int mrow = row0 + wm * 32 + mt * 16 + (lane >> 2);
        #pragma unroll
        for (int nt = 0; nt < 8; nt++) {
            int ncol = col0 + wn * 64 + nt * 8 + (lane & 3) * 2;
            float bx = b2[ncol], by = b2[ncol + 1];
            float2 v0 = make_float2(acc[mt][nt][0] + bx, acc[mt][nt][1] + by);
            float2 v1 = make_float2(acc[mt][nt][2] + bx, acc[mt][nt][3] + by);
            *(float2*)&out[(size_t)mrow * EMB + ncol]       = v0;
            *(float2*)&out[(size_t)(mrow + 8) * EMB + ncol] = v1;
        }
    }
}

// ---- launcher ----------------------------------------------------------------
extern "C" void kernel_launch(void* const* d_in, const int* in_sizes, int n_in,
                              void* d_out, int out_size)
{
    const float *x = 0, *theta = 0, *W1 = 0, *b1 = 0, *W2 = 0, *b2 = 0;
    for (int i = 0; i < n_in; i++) {
        switch (in_sizes[i]) {
            case BS * NQ:   x     = (const float*)d_in[i]; break;
            case NQ:        theta = (const float*)d_in[i]; break;
            case NQ * FFN:  W1    = (const float*)d_in[i]; break;
            case FFN:       b1    = (const float*)d_in[i]; break;
            case FFN * EMB: W2    = (const float*)d_in[i]; break;
            case EMB:       b2    = (const float*)d_in[i]; break;
            default: break;
        }
    }

    prep_w2_kernel<<<(EMB * FFN + 255) / 256, 256>>>(W2);
    h_kernel<<<BS / TB, 256>>>(x, theta, W1, b1);

    cudaFuncSetAttribute(gemm_kernel, cudaFuncAttributeMaxDynamicSharedMemorySize,
                         SMEM_BYTES);
    dim3 grid(EMB / TNT, BS / TMT);   // 4 x 256; col-fastest for L2 A reuse
    gemm_kernel<<<grid, NTH, SMEM_BYTES>>>(b2, (float*)d_out);
}

// round 6
// speedup vs baseline: 3.4463x; 2.4926x over previous
#include <cuda_runtime.h>
#include <cuda_fp16.h>
#include <cstdint>
#include <math.h>

#define BS   32768
#define NQ   8
#define FFN  2048
#define EMB  512

#define TMT  128              // tokens per CTA (GEMM)
#define TNT  128              // out cols per CTA
#define KC   64               // FFN chunk per iteration (4 x k16 mma steps)
#define NC   (FFN / KC)       // 32 iterations
#define NTH  512
#define ROWB 144              // 128B data + 16B pad -> ldmatrix conflict-free
#define NSTAGE 2

// scratch: H fp16 [BS][FFN], W2 transposed fp16 [EMB][FFN]
__device__ __half g_h[BS * FFN];
__device__ __half g_w2t[EMB * FFN];

// ---- smem: 2 stages x (A 128x144 + B 128x144) ----
#define SM_A(s)  ((s) * 36864)
#define SM_B(s)  ((s) * 36864 + 18432)
#define SMEM_BYTES 73728

__device__ __forceinline__ uint32_t smem_u32(const void* p) {
    uint32_t a;
    asm("{ .reg .u64 t; cvta.to.shared.u64 t, %1; cvt.u32.u64 %0, t; }" : "=r"(a) : "l"(p));
    return a;
}

#define LDSM4(r, a)                                                            \
    asm volatile("ldmatrix.sync.aligned.m8n8.x4.shared.b16 {%0,%1,%2,%3}, [%4];" \
        : "=r"((r)[0]), "=r"((r)[1]), "=r"((r)[2]), "=r"((r)[3]) : "r"(a))

#define MMAF16(d, a, b0, b1v)                                                  \
    asm volatile("mma.sync.aligned.m16n8k16.row.col.f32.f16.f16.f32 "         \
        "{%0,%1,%2,%3},{%4,%5,%6,%7},{%8,%9},{%0,%1,%2,%3};"                  \
        : "+f"((d)[0]), "+f"((d)[1]), "+f"((d)[2]), "+f"((d)[3])              \
        : "r"((a)[0]), "r"((a)[1]), "r"((a)[2]), "r"((a)[3]), "r"(b0), "r"(b1v))

#define CP16(dst, src)                                                         \
    asm volatile("cp.async.cg.shared.global [%0], [%1], 16;" :: "r"(dst), "l"(src))
#define CP_COMMIT() asm volatile("cp.async.commit_group;" ::: "memory")
#define CP_WAIT1()  asm volatile("cp.async.wait_group 1;" ::: "memory")

// ---- prep: W2 [FFN][EMB] fp32 -> fp16 transposed [EMB][FFN] ----------------
__global__ void prep_w2_kernel(const float* __restrict__ W2) {
    int t = blockIdx.x * blockDim.x + threadIdx.x;
    if (t >= EMB * FFN) return;
    int n = t >> 11;
    int k = t & (FFN - 1);
    g_w2t[t] = __float2half_rn(W2[(size_t)k * EMB + n]);
}

// ---- kernel 1: H = fp16(relu(q @ W1 + b1)), q = cos(x)*cos(theta) ----------
#define TB 64
__global__ __launch_bounds__(256, 4)
void h_kernel(const float* __restrict__ x,
              const float* __restrict__ theta,
              const float* __restrict__ W1,
              const float* __restrict__ b1)
{
    __shared__ float q_s[TB][NQ];
    const int tid  = threadIdx.x;
    const int row0 = blockIdx.x * TB;
    const int k0   = tid * 8;

    #pragma unroll
    for (int i = tid; i < TB * NQ; i += 256) {
        int m = i >> 3, j = i & 7;
        q_s[m][j] = cosf(x[(size_t)(row0 + m) * NQ + j]) * cosf(__ldg(&theta[j]));
    }

    float w1r[8][NQ];
    float b1r[8];
    #pragma unroll
    for (int u = 0; u < 8; u++) {
        b1r[u] = __ldg(&b1[k0 + u]);
        #pragma unroll
        for (int j = 0; j < NQ; j++)
            w1r[u][j] = __ldg(&W1[(size_t)j * FFN + k0 + u]);
    }
    __syncthreads();

    for (int t = 0; t < TB; t++) {
        float4 qa = *(const float4*)&q_s[t][0];
        float4 qb = *(const float4*)&q_s[t][4];
        uint32_t w[4];
        #pragma unroll
        for (int u = 0; u < 8; u++) {
            float s = b1r[u];
            s = fmaf(qa.x, w1r[u][0], s); s = fmaf(qa.y, w1r[u][1], s);
            s = fmaf(qa.z, w1r[u][2], s); s = fmaf(qa.w, w1r[u][3], s);
            s = fmaf(qb.x, w1r[u][4], s); s = fmaf(qb.y, w1r[u][5], s);
            s = fmaf(qb.z, w1r[u][6], s); s = fmaf(qb.w, w1r[u][7], s);
            s = fmaxf(s, 0.f);
            uint32_t hb = (uint32_t)__half_as_ushort(__float2half_rn(s));
            if (u & 1) w[u >> 1] |= hb << 16;
            else       w[u >> 1]  = hb;
        }
        *(uint4*)((char*)(g_h + (size_t)(row0 + t) * FFN) + tid * 16)
            = make_uint4(w[0], w[1], w[2], w[3]);
    }
}

// ---- kernel 2: out = H @ W2 + b2, plain fp16 MMA, fp32 accum ---------------
__global__ __launch_bounds__(NTH, 2)
void gemm_kernel(const float* __restrict__ b2, float* __restrict__ out)
{
    extern __shared__ char sm[];
    const uint32_t smb = smem_u32(sm);

    const int tid  = threadIdx.x;
    const int wid  = tid >> 5;
    const int lane = tid & 31;
    const int col0 = blockIdx.x * TNT;      // x fastest: 4 col CTAs share A via L2
    const int row0 = blockIdx.y * TMT;
    const int wm   = wid & 3;               // 4 M groups of 32 rows
    const int wn   = wid >> 2;              // 4 N groups of 32 cols

    // ldmatrix lane addresses
    const uint32_t a_off = (uint32_t)(wm * 32 + (lane & 15)) * ROWB + ((lane >> 4) << 4);
    const uint32_t b_off = (uint32_t)(wn * 32 + (lane & 7) + ((lane & 16) >> 1)) * ROWB
                         + ((lane & 8) << 1);

    // cp.async: thread covers row = tid>>2, 32B segment = (tid&3)*32
    const int ldr = tid >> 2;
    const int lds = (tid & 3) * 32;         // byte offset within 128B row chunk
    const char* gA = (const char*)(g_h  + (size_t)(row0 + ldr) * FFN) + lds;
    const char* gB = (const char*)(g_w2t + (size_t)(col0 + ldr) * FFN) + lds;
    const uint32_t soA = (uint32_t)ldr * ROWB + lds;

    float acc[2][4][4];
    #pragma unroll
    for (int a = 0; a < 2; a++)
        #pragma unroll
        for (int b = 0; b < 4; b++)
            #pragma unroll
            for (int i = 0; i < 4; i++) acc[a][b][i] = 0.f;

    // prologue: stage 0 = chunk 0
    {
        CP16(smb + SM_A(0) + soA,      gA);
        CP16(smb + SM_A(0) + soA + 16, gA + 16);
        CP16(smb + SM_B(0) + soA,      gB);
        CP16(smb + SM_B(0) + soA + 16, gB + 16);
        CP_COMMIT();
    }

    for (int c = 0; c < NC; c++) {
        const int s = c & 1;

        // prefetch chunk c+1 into the other stage (consumed+synced last iter)
        if (c + 1 < NC) {
            const char* a = gA + (c + 1) * (KC * 2);
            const char* b = gB + (c + 1) * (KC * 2);
            CP16(smb + SM_A(s ^ 1) + soA,      a);
            CP16(smb + SM_A(s ^ 1) + soA + 16, a + 16);
            CP16(smb + SM_B(s ^ 1) + soA,      b);
            CP16(smb + SM_B(s ^ 1) + soA + 16, b + 16);
        }
        CP_COMMIT();
        CP_WAIT1();             // chunk c landed; c+1 may stay in flight
        __syncthreads();

        const uint32_t A = smb + SM_A(s) + a_off;
        const uint32_t B = smb + SM_B(s) + b_off;
        #pragma unroll
        for (int ks = 0; ks < 4; ks++) {
            uint32_t ah[2][4];
            LDSM4(ah[0], A + ks * 32);
            LDSM4(ah[1], A + ks * 32 + 16 * ROWB);
            #pragma unroll
            for (int g = 0; g < 2; g++) {
                uint32_t bh[4];
                LDSM4(bh, B + g * 16 * ROWB + ks * 32);
                MMAF16(acc[0][2 * g],     ah[0], bh[0], bh[1]);
                MMAF16(acc[1][2 * g],     ah[1], bh[0], bh[1]);
                MMAF16(acc[0][2 * g + 1], ah[0], bh[2], bh[3]);
                MMAF16(acc[1][2 * g + 1], ah[1], bh[2], bh[3]);
            }
        }
        __syncthreads();        // stage s free for prefetch next iter
    }

    // epilogue: D frags + b2
    #pragma unroll
    for (int mt = 0; mt < 2; mt++) {
        int mrow = row0 + wm * 32 + mt * 16 + (lane >> 2);
        #pragma unroll
        for (int nt = 0; nt < 4; nt++) {
            int ncol = col0 + wn * 32 + nt * 8 + (lane & 3) * 2;
            float bx = b2[ncol], by = b2[ncol + 1];
            float2 v0 = make_float2(acc[mt][nt][0] + bx, acc[mt][nt][1] + by);
            float2 v1 = make_float2(acc[mt][nt][2] + bx, acc[mt][nt][3] + by);
            *(float2*)&out[(size_t)mrow * EMB + ncol]       = v0;
            *(float2*)&out[(size_t)(mrow + 8) * EMB + ncol] = v1;
        }
    }
}

// ---- launcher ----------------------------------------------------------------
extern "C" void kernel_launch(void* const* d_in, const int* in_sizes, int n_in,
                              void* d_out, int out_size)
{
    const float *x = 0, *theta = 0, *W1 = 0, *b1 = 0, *W2 = 0, *b2 = 0;
    for (int i = 0; i < n_in; i++) {
        switch (in_sizes[i]) {
            case BS * NQ:   x     = (const float*)d_in[i]; break;
            case NQ:        theta = (const float*)d_in[i]; break;
            case NQ * FFN:  W1    = (const float*)d_in[i]; break;
            case FFN:       b1    = (const float*)d_in[i]; break;
            case FFN * EMB: W2    = (const float*)d_in[i]; break;
            case EMB:       b2    = (const float*)d_in[i]; break;
            default: break;
        }
    }

    prep_w2_kernel<<<(EMB * FFN + 255) / 256, 256>>>(W2);
    h_kernel<<<BS / TB, 256>>>(x, theta, W1, b1);

    cudaFuncSetAttribute(gemm_kernel, cudaFuncAttributeMaxDynamicSharedMemorySize,
                         SMEM_BYTES);
    dim3 grid(EMB / TNT, BS / TMT);   // 4 x 256; col-fastest for L2 A reuse
    gemm_kernel<<<grid, NTH, SMEM_BYTES>>>(b2, (float*)d_out);
}

// round 7
// speedup vs baseline: 3.6059x; 1.0463x over previous
#include <cuda_runtime.h>
#include <cuda_fp16.h>
#include <cstdint>
#include <math.h>

#define BS   32768
#define NQ   8
#define FFN  2048
#define EMB  512

#define TMT  128              // tokens per CTA (GEMM)
#define TNT  128              // out cols per CTA
#define KC   64               // FFN chunk per iteration (4 x k16 mma steps)
#define NC   (FFN / KC)       // 32 iterations
#define NTH  128              // 4 warps, 2x2 grid of 64x64 warp tiles
#define ROWB 144              // 128B data + 16B pad -> ldmatrix conflict-free

// scratch: H fp16 [BS][FFN], W2 transposed fp16 [EMB][FFN]
__device__ __half g_h[BS * FFN];
__device__ __half g_w2t[EMB * FFN];

// ---- smem: 2 stages x (A 128x144 + B 128x144) = 72 KB ----
#define SM_A(s)  ((s) * 36864)
#define SM_B(s)  ((s) * 36864 + 18432)
#define SMEM_BYTES 73728

__device__ __forceinline__ uint32_t smem_u32(const void* p) {
    uint32_t a;
    asm("{ .reg .u64 t; cvta.to.shared.u64 t, %1; cvt.u32.u64 %0, t; }" : "=r"(a) : "l"(p));
    return a;
}

#define LDSM4(r, a)                                                            \
    asm volatile("ldmatrix.sync.aligned.m8n8.x4.shared.b16 {%0,%1,%2,%3}, [%4];" \
        : "=r"((r)[0]), "=r"((r)[1]), "=r"((r)[2]), "=r"((r)[3]) : "r"(a))

#define MMAF16(d, a, b0, b1v)                                                  \
    asm volatile("mma.sync.aligned.m16n8k16.row.col.f32.f16.f16.f32 "         \
        "{%0,%1,%2,%3},{%4,%5,%6,%7},{%8,%9},{%0,%1,%2,%3};"                  \
        : "+f"((d)[0]), "+f"((d)[1]), "+f"((d)[2]), "+f"((d)[3])              \
        : "r"((a)[0]), "r"((a)[1]), "r"((a)[2]), "r"((a)[3]), "r"(b0), "r"(b1v))

#define CP16(dst, src)                                                         \
    asm volatile("cp.async.cg.shared.global [%0], [%1], 16;" :: "r"(dst), "l"(src))
#define CP_COMMIT() asm volatile("cp.async.commit_group;" ::: "memory")
#define CP_WAIT1()  asm volatile("cp.async.wait_group 1;" ::: "memory")

// ---- pre kernel: fused W2 transpose/convert + H compute --------------------
// blocks [0, 4096):  g_w2t[n][k] = fp16(W2[k][n])
// blocks [4096, 4608): H = fp16(relu(q @ W1 + b1)), 64 tokens per block
#define TB 64
#define PREP_BLOCKS (EMB * FFN / 256)      // 4096
__global__ __launch_bounds__(256, 4)
void pre_kernel(const float* __restrict__ x,
                const float* __restrict__ theta,
                const float* __restrict__ W1,
                const float* __restrict__ b1,
                const float* __restrict__ W2)
{
    const int tid = threadIdx.x;

    if (blockIdx.x < PREP_BLOCKS) {
        int t = blockIdx.x * 256 + tid;
        int n = t >> 11;
        int k = t & (FFN - 1);
        g_w2t[t] = __float2half_rn(W2[(size_t)k * EMB + n]);
        return;
    }

    __shared__ float q_s[TB][NQ];
    const int row0 = (blockIdx.x - PREP_BLOCKS) * TB;
    const int k0   = tid * 8;

    #pragma unroll
    for (int i = tid; i < TB * NQ; i += 256) {
        int m = i >> 3, j = i & 7;
        q_s[m][j] = cosf(x[(size_t)(row0 + m) * NQ + j]) * cosf(__ldg(&theta[j]));
    }

    float w1r[8][NQ];
    float b1r[8];
    #pragma unroll
    for (int u = 0; u < 8; u++) {
        b1r[u] = __ldg(&b1[k0 + u]);
        #pragma unroll
        for (int j = 0; j < NQ; j++)
            w1r[u][j] = __ldg(&W1[(size_t)j * FFN + k0 + u]);
    }
    __syncthreads();

    for (int t = 0; t < TB; t++) {
        float4 qa = *(const float4*)&q_s[t][0];
        float4 qb = *(const float4*)&q_s[t][4];
        uint32_t w[4];
        #pragma unroll
        for (int u = 0; u < 8; u++) {
            float s = b1r[u];
            s = fmaf(qa.x, w1r[u][0], s); s = fmaf(qa.y, w1r[u][1], s);
            s = fmaf(qa.z, w1r[u][2], s); s = fmaf(qa.w, w1r[u][3], s);
            s = fmaf(qb.x, w1r[u][4], s); s = fmaf(qb.y, w1r[u][5], s);
            s = fmaf(qb.z, w1r[u][6], s); s = fmaf(qb.w, w1r[u][7], s);
            s = fmaxf(s, 0.f);
            uint32_t hb = (uint32_t)__half_as_ushort(__float2half_rn(s));
            if (u & 1) w[u >> 1] |= hb << 16;
            else       w[u >> 1]  = hb;
        }
        *(uint4*)((char*)(g_h + (size_t)(row0 + t) * FFN) + tid * 16)
            = make_uint4(w[0], w[1], w[2], w[3]);
    }
}

// ---- gemm: out = H @ W2 + b2, fp16 MMA / fp32 accum, 64x64 warp tiles ------
__global__ __launch_bounds__(NTH, 2)
void gemm_kernel(const float* __restrict__ b2, float* __restrict__ out)
{
    extern __shared__ char sm[];
    const uint32_t smb = smem_u32(sm);

    const int tid  = threadIdx.x;
    const int wid  = tid >> 5;
    const int lane = tid & 31;
    const int col0 = blockIdx.x * TNT;      // x fastest: 4 col CTAs share A via L2
    const int row0 = blockIdx.y * TMT;
    const int wm   = wid & 1;               // 2 M groups of 64 rows
    const int wn   = wid >> 1;              // 2 N groups of 64 cols

    // ldmatrix lane addresses (mapping verified in R3-R6)
    const uint32_t a_off = (uint32_t)(wm * 64 + (lane & 15)) * ROWB + ((lane >> 4) << 4);
    const uint32_t b_off = (uint32_t)(wn * 64 + (lane & 7) + ((lane & 16) >> 1)) * ROWB
                         + ((lane & 8) << 1);

    // cp.async: thread covers row = tid>>3 (+16*r), 16B segment = tid&7
    const int ldr = tid >> 3;
    const int seg = (tid & 7) * 16;
    const char* gA = (const char*)(g_h   + (size_t)(row0 + ldr) * FFN) + seg;
    const char* gB = (const char*)(g_w2t + (size_t)(col0 + ldr) * FFN) + seg;
    const uint32_t soA = (uint32_t)ldr * ROWB + seg;

    auto issue = [&](int chunk, int s) {
        const char* a = gA + chunk * (KC * 2);
        const char* b = gB + chunk * (KC * 2);
        #pragma unroll
        for (int r = 0; r < 8; r++) {       // rows ldr + 16*r
            CP16(smb + SM_A(s) + soA + r * 16 * ROWB, a + (size_t)r * 16 * FFN * 2);
            CP16(smb + SM_B(s) + soA + r * 16 * ROWB, b + (size_t)r * 16 * FFN * 2);
        }
    };

    float acc[4][8][4];
    #pragma unroll
    for (int a = 0; a < 4; a++)
        #pragma unroll
        for (int b = 0; b < 8; b++)
            #pragma unroll
            for (int i = 0; i < 4; i++) acc[a][b][i] = 0.f;

    // prologue: stage 0 = chunk 0
    issue(0, 0);
    CP_COMMIT();

    for (int c = 0; c < NC; c++) {
        const int s = c & 1;

        if (c + 1 < NC) issue(c + 1, s ^ 1);
        CP_COMMIT();
        CP_WAIT1();             // chunk c landed; c+1 may stay in flight
        __syncthreads();

        const uint32_t A = smb + SM_A(s) + a_off;
        const uint32_t B = smb + SM_B(s) + b_off;
        #pragma unroll
        for (int ks = 0; ks < 4; ks++) {
            uint32_t ah[4][4];
            #pragma unroll
            for (int mt = 0; mt < 4; mt++)
                LDSM4(ah[mt], A + mt * 16 * ROWB + ks * 32);
            #pragma unroll
            for (int g = 0; g < 4; g++) {
                uint32_t bh[4];
                LDSM4(bh, B + g * 16 * ROWB + ks * 32);
                #pragma unroll
                for (int mt = 0; mt < 4; mt++) {
                    MMAF16(acc[mt][2 * g],     ah[mt], bh[0], bh[1]);
                    MMAF16(acc[mt][2 * g + 1], ah[mt], bh[2], bh[3]);
                }
            }
        }
        __syncthreads();        // stage s free for prefetch next iter
    }

    // epilogue: D frags + b2
    #pragma unroll
    for (int mt = 0; mt < 4; mt++) {
        int mrow = row0 + wm * 64 + mt * 16 + (lane >> 2);
        #pragma unroll
        for (int nt = 0; nt < 8; nt++) {
            int ncol = col0 + wn * 64 + nt * 8 + (lane & 3) * 2;
            float bx = b2[ncol], by = b2[ncol + 1];
            float2 v0 = make_float2(acc[mt][nt][0] + bx, acc[mt][nt][1] + by);
            float2 v1 = make_float2(acc[mt][nt][2] + bx, acc[mt][nt][3] + by);
            *(float2*)&out[(size_t)mrow * EMB + ncol]       = v0;
            *(float2*)&out[(size_t)(mrow + 8) * EMB + ncol] = v1;
        }
    }
}

// ---- launcher ----------------------------------------------------------------
extern "C" void kernel_launch(void* const* d_in, const int* in_sizes, int n_in,
                              void* d_out, int out_size)
{
    const float *x = 0, *theta = 0, *W1 = 0, *b1 = 0, *W2 = 0, *b2 = 0;
    for (int i = 0; i < n_in; i++) {
        switch (in_sizes[i]) {
            case BS * NQ:   x     = (const float*)d_in[i]; break;
            case NQ:        theta = (const float*)d_in[i]; break;
            case NQ * FFN:  W1    = (const float*)d_in[i]; break;
            case FFN:       b1    = (const float*)d_in[i]; break;
            case FFN * EMB: W2    = (const float*)d_in[i]; break;
            case EMB:       b2    = (const float*)d_in[i]; break;
            default: break;
        }
    }

    pre_kernel<<<PREP_BLOCKS + BS / TB, 256>>>(x, theta, W1, b1, W2);

    cudaFuncSetAttribute(gemm_kernel, cudaFuncAttributeMaxDynamicSharedMemorySize,
                         SMEM_BYTES);
    dim3 grid(EMB / TNT, BS / TMT);   // 4 x 256; col-fastest for L2 A reuse
    gemm_kernel<<<grid, NTH, SMEM_BYTES>>>(b2, (float*)d_out);
}

// round 8
// speedup vs baseline: 4.5308x; 1.2565x over previous
#include <cuda_runtime.h>
#include <cuda_fp16.h>
#include <cstdint>
#include <math.h>

#define BS   32768
#define NQ   8
#define FFN  2048
#define EMB  512

#define TMT  128              // tokens per CTA (GEMM)
#define TNT  128              // out cols per CTA
#define KC   64               // FFN chunk per iteration (4 x k16 mma steps)
#define NC   (FFN / KC)       // 32 iterations
#define NTH  128              // 4 warps, 2x2 grid of 64x64 warp tiles
#define ROWB 144              // 128B data + 16B pad -> ldmatrix conflict-free

// scratch: H fp16 [BS][FFN], W2 transposed fp16 [EMB][FFN]
__device__ __half g_h[BS * FFN];
__device__ __half g_w2t[EMB * FFN];

// ---- smem: 2 stages x (A 128x144 + B 128x144) = 72 KB ----
#define SM_A(s)  ((s) * 36864)
#define SM_B(s)  ((s) * 36864 + 18432)
#define SMEM_BYTES 73728

__device__ __forceinline__ uint32_t smem_u32(const void* p) {
    uint32_t a;
    asm("{ .reg .u64 t; cvta.to.shared.u64 t, %1; cvt.u32.u64 %0, t; }" : "=r"(a) : "l"(p));
    return a;
}

#define LDSM4(r, a)                                                            \
    asm volatile("ldmatrix.sync.aligned.m8n8.x4.shared.b16 {%0,%1,%2,%3}, [%4];" \
        : "=r"((r)[0]), "=r"((r)[1]), "=r"((r)[2]), "=r"((r)[3]) : "r"(a))

#define MMAF16(d, a, b0, b1v)                                                  \
    asm volatile("mma.sync.aligned.m16n8k16.row.col.f32.f16.f16.f32 "         \
        "{%0,%1,%2,%3},{%4,%5,%6,%7},{%8,%9},{%0,%1,%2,%3};"                  \
        : "+f"((d)[0]), "+f"((d)[1]), "+f"((d)[2]), "+f"((d)[3])              \
        : "r"((a)[0]), "r"((a)[1]), "r"((a)[2]), "r"((a)[3]), "r"(b0), "r"(b1v))

#define CP16(dst, src)                                                         \
    asm volatile("cp.async.cg.shared.global [%0], [%1], 16;" :: "r"(dst), "l"(src))
#define CP_COMMIT() asm volatile("cp.async.commit_group;" ::: "memory")
#define CP_WAIT1()  asm volatile("cp.async.wait_group 1;" ::: "memory")

// ---- prep: W2 [FFN][EMB] fp32 -> fp16 transposed [EMB][FFN] ----------------
__global__ void prep_w2_kernel(const float* __restrict__ W2) {
    int t = blockIdx.x * blockDim.x + threadIdx.x;
    if (t >= EMB * FFN) return;
    int n = t >> 11;
    int k = t & (FFN - 1);
    g_w2t[t] = __float2half_rn(W2[(size_t)k * EMB + n]);
}

// ---- kernel 1: H = fp16(relu(q @ W1 + b1)) ---------------------------------
// occupancy 2 (128 regs) so the 64-float W1 slice stays register-resident.
#define TB 64
__global__ __launch_bounds__(256, 2)
void h_kernel(const float* __restrict__ x,
              const float* __restrict__ theta,
              const float* __restrict__ W1,
              const float* __restrict__ b1)
{
    __shared__ float q_s[TB][NQ];
    const int tid  = threadIdx.x;
    const int row0 = blockIdx.x * TB;
    const int k0   = tid * 8;

    #pragma unroll
    for (int i = tid; i < TB * NQ; i += 256) {
        int m = i >> 3, j = i & 7;
        q_s[m][j] = cosf(x[(size_t)(row0 + m) * NQ + j]) * cosf(__ldg(&theta[j]));
    }

    float w1r[8][NQ];
    float b1r[8];
    #pragma unroll
    for (int u = 0; u < 8; u++) {
        b1r[u] = __ldg(&b1[k0 + u]);
        #pragma unroll
        for (int j = 0; j < NQ; j++)
            w1r[u][j] = __ldg(&W1[(size_t)j * FFN + k0 + u]);
    }
    __syncthreads();

    for (int t = 0; t < TB; t++) {
        float4 qa = *(const float4*)&q_s[t][0];
        float4 qb = *(const float4*)&q_s[t][4];
        uint32_t w[4];
        #pragma unroll
        for (int u = 0; u < 8; u++) {
            float s = b1r[u];
            s = fmaf(qa.x, w1r[u][0], s); s = fmaf(qa.y, w1r[u][1], s);
            s = fmaf(qa.z, w1r[u][2], s); s = fmaf(qa.w, w1r[u][3], s);
            s = fmaf(qb.x, w1r[u][4], s); s = fmaf(qb.y, w1r[u][5], s);
            s = fmaf(qb.z, w1r[u][6], s); s = fmaf(qb.w, w1r[u][7], s);
            s = fmaxf(s, 0.f);
            uint32_t hb = (uint32_t)__half_as_ushort(__float2half_rn(s));
            if (u & 1) w[u >> 1] |= hb << 16;
            else       w[u >> 1]  = hb;
        }
        *(uint4*)((char*)(g_h + (size_t)(row0 + t) * FFN) + tid * 16)
            = make_uint4(w[0], w[1], w[2], w[3]);
    }
}

// ---- gemm: out = H @ W2 + b2, fp16 MMA / fp32 accum, 64x64 warp tiles ------
// occupancy 3: ptxas caps regs at 170 (acc=128 + frags fit), smem 3x72KB=216KB.
__global__ __launch_bounds__(NTH, 3)
void gemm_kernel(const float* __restrict__ b2, float* __restrict__ out)
{
    extern __shared__ char sm[];
    const uint32_t smb = smem_u32(sm);

    const int tid  = threadIdx.x;
    const int wid  = tid >> 5;
    const int lane = tid & 31;
    const int col0 = blockIdx.x * TNT;      // x fastest: 4 col CTAs share A via L2
    const int row0 = blockIdx.y * TMT;
    const int wm   = wid & 1;               // 2 M groups of 64 rows
    const int wn   = wid >> 1;              // 2 N groups of 64 cols

    const uint32_t a_off = (uint32_t)(wm * 64 + (lane & 15)) * ROWB + ((lane >> 4) << 4);
    const uint32_t b_off = (uint32_t)(wn * 64 + (lane & 7) + ((lane & 16) >> 1)) * ROWB
                         + ((lane & 8) << 1);

    // cp.async: thread covers row = tid>>3 (+16*r), 16B segment = tid&7
    const int ldr = tid >> 3;
    const int seg = (tid & 7) * 16;
    const char* gA = (const char*)(g_h   + (size_t)(row0 + ldr) * FFN) + seg;
    const char* gB = (const char*)(g_w2t + (size_t)(col0 + ldr) * FFN) + seg;
    const uint32_t soA = (uint32_t)ldr * ROWB + seg;

    auto issue = [&](int chunk, int s) {
        const char* a = gA + chunk * (KC * 2);
        const char* b = gB + chunk * (KC * 2);
        #pragma unroll
        for (int r = 0; r < 8; r++) {       // rows ldr + 16*r
            CP16(smb + SM_A(s) + soA + r * 16 * ROWB, a + (size_t)r * 16 * FFN * 2);
            CP16(smb + SM_B(s) + soA + r * 16 * ROWB, b + (size_t)r * 16 * FFN * 2);
        }
    };

    float acc[4][8][4];
    #pragma unroll
    for (int a = 0; a < 4; a++)
        #pragma unroll
        for (int b = 0; b < 8; b++)
            #pragma unroll
            for (int i = 0; i < 4; i++) acc[a][b][i] = 0.f;

    issue(0, 0);
    CP_COMMIT();

    for (int c = 0; c < NC; c++) {
        const int s = c & 1;

        if (c + 1 < NC) issue(c + 1, s ^ 1);
        CP_COMMIT();
        CP_WAIT1();             // chunk c landed; c+1 may stay in flight
        __syncthreads();

        const uint32_t A = smb + SM_A(s) + a_off;
        const uint32_t B = smb + SM_B(s) + b_off;
        #pragma unroll
        for (int ks = 0; ks < 4; ks++) {
            uint32_t ah[4][4];
            #pragma unroll
            for (int mt = 0; mt < 4; mt++)
                LDSM4(ah[mt], A + mt * 16 * ROWB + ks * 32);
            #pragma unroll
            for (int g = 0; g < 4; g++) {
                uint32_t bh[4];
                LDSM4(bh, B + g * 16 * ROWB + ks * 32);
                #pragma unroll
                for (int mt = 0; mt < 4; mt++) {
                    MMAF16(acc[mt][2 * g],     ah[mt], bh[0], bh[1]);
                    MMAF16(acc[mt][2 * g + 1], ah[mt], bh[2], bh[3]);
                }
            }
        }
        __syncthreads();        // stage s free for prefetch next iter
    }

    // epilogue: D frags + b2
    #pragma unroll
    for (int mt = 0; mt < 4; mt++) {
        int mrow = row0 + wm * 64 + mt * 16 + (lane >> 2);
        #pragma unroll
        for (int nt = 0; nt < 8; nt++) {
            int ncol = col0 + wn * 64 + nt * 8 + (lane & 3) * 2;
            float bx = b2[ncol], by = b2[ncol + 1];
            float2 v0 = make_float2(acc[mt][nt][0] + bx, acc[mt][nt][1] + by);
            float2 v1 = make_float2(acc[mt][nt][2] + bx, acc[mt][nt][3] + by);
            *(float2*)&out[(size_t)mrow * EMB + ncol]       = v0;
            *(float2*)&out[(size_t)(mrow + 8) * EMB + ncol] = v1;
        }
    }
}

// ---- launcher ----------------------------------------------------------------
extern "C" void kernel_launch(void* const* d_in, const int* in_sizes, int n_in,
                              void* d_out, int out_size)
{
    const float *x = 0, *theta = 0, *W1 = 0, *b1 = 0, *W2 = 0, *b2 = 0;
    for (int i = 0; i < n_in; i++) {
        switch (in_sizes[i]) {
            case BS * NQ:   x     = (const float*)d_in[i]; break;
            case NQ:        theta = (const float*)d_in[i]; break;
            case NQ * FFN:  W1    = (const float*)d_in[i]; break;
            case FFN:       b1    = (const float*)d_in[i]; break;
            case FFN * EMB: W2    = (const float*)d_in[i]; break;
            case EMB:       b2    = (const float*)d_in[i]; break;
            default: break;
        }
    }

    prep_w2_kernel<<<(EMB * FFN + 255) / 256, 256>>>(W2);
    h_kernel<<<BS / TB, 256>>>(x, theta, W1, b1);

    cudaFuncSetAttribute(gemm_kernel, cudaFuncAttributeMaxDynamicSharedMemorySize,
                         SMEM_BYTES);
    dim3 grid(EMB / TNT, BS / TMT);   // 4 x 256; col-fastest for L2 A reuse
    gemm_kernel<<<grid, NTH, SMEM_BYTES>>>(b2, (float*)d_out);
}